// round 1
// baseline (speedup 1.0000x reference)
#include <cuda_runtime.h>

#define TM1 262143           // T-1 output timesteps
#define PRE_TCHUNK 128

typedef unsigned long long ull;

// Scratch (allocation-free rule: __device__ globals)
__device__ float g_pre0[(size_t)TM1 * 256];   // layer0 input-side preactivations [t][4H]
__device__ float g_h2[(size_t)TM1 * 64];      // layer1 hidden trace for FC

// ---------------- fast math helpers ----------------
__device__ __forceinline__ void ffma2(ull& acc, ull a, ull b) {
    asm("fma.rn.f32x2 %0, %1, %2, %0;" : "+l"(acc) : "l"(a), "l"(b));
}
__device__ __forceinline__ float hsum2(ull a) {
    float lo, hi;
    asm("mov.b64 {%0,%1}, %2;" : "=f"(lo), "=f"(hi) : "l"(a));
    return lo + hi;
}
__device__ __forceinline__ float fast_ex2(float x) {
    float r; asm("ex2.approx.f32 %0, %1;" : "=f"(r) : "f"(x)); return r;
}
__device__ __forceinline__ float fast_rcp(float x) {
    float r; asm("rcp.approx.f32 %0, %1;" : "=f"(r) : "f"(x)); return r;
}
// sigmoid(x) = 1/(1+2^(-x*log2e)); ex2/rcp approx err ~2^-22 (tanh.approx is 2^-11: too coarse)
__device__ __forceinline__ float sigm(float x) {
    return fast_rcp(1.0f + fast_ex2(-1.4426950408889634f * x));
}
// tanh(x) = 1 - 2/(2^(2x*log2e)+1); saturates correctly via inf/0 at extremes
__device__ __forceinline__ float tanh_(float x) {
    float e = fast_ex2(2.8853900817779268f * x);
    return 1.0f - 2.0f * fast_rcp(e + 1.0f);
}

// ---------------- phase 1: parallel input-side preactivations ----------------
// pre0[t][r] = b_ih0[r]+b_hh0[r] + sum_j W_ih0[r][j] * padded[t+j]
// padded = [1,1,1,1,1, y[0..]]  (INPUT_SIZE=6 sliding window)
__global__ __launch_bounds__(256)
void pre0_kernel(const float* __restrict__ y,
                 const float* __restrict__ Wih0,
                 const float* __restrict__ bih0,
                 const float* __restrict__ bhh0)
{
    __shared__ float sy[PRE_TCHUNK + 8];
    const int r = threadIdx.x;
    const int t0 = blockIdx.x * PRE_TCHUNK;
    int t1 = t0 + PRE_TCHUNK; if (t1 > TM1) t1 = TM1;

    // stage the padded-signal window once
    for (int i = r; i < PRE_TCHUNK + 5; i += 256) {
        int idx = t0 + i;                    // padded index
        sy[i] = (idx < 5) ? 1.0f : y[idx - 5];
    }

    float w[6];
#pragma unroll
    for (int j = 0; j < 6; j++) w[j] = Wih0[r * 6 + j];
    const float b = bih0[r] + bhh0[r];
    __syncthreads();

    for (int t = t0; t < t1; t++) {
        float acc = b;
#pragma unroll
        for (int j = 0; j < 6; j++)
            acc = fmaf(w[j], sy[t - t0 + j], acc);
        g_pre0[(size_t)t * 256 + r] = acc;
    }
}

// ---------------- phase 2: serial 2-layer LSTM (single CTA) ----------------
// thread r in [0,256) owns gate-row r. All recurrent weights register-resident:
//   w0  = W_hh0[r][:]   (64 f -> 32 packed f32x2)
//   wi1 = W_ih1[r][:], wh1 = W_hh1[r][:]
// Per step: 96 fma.rn.f32x2 per thread; h vectors broadcast from smem via 16B loads.
__global__ __launch_bounds__(256, 1)
void lstm_seq_kernel(const float* __restrict__ Whh0,
                     const float* __restrict__ Wih1,
                     const float* __restrict__ Whh1,
                     const float* __restrict__ bih1,
                     const float* __restrict__ bhh1)
{
    __shared__ __align__(16) float sh0[64];   // layer0 hidden state
    __shared__ __align__(16) float sh1[64];   // layer1 hidden state
    __shared__ float sg[256];                 // gate scratch

    const int r = threadIdx.x;

    ull w0[32], wi1[32], wh1[32];
    {
        const ull* p0 = (const ull*)(Whh0 + r * 64);
        const ull* p1 = (const ull*)(Wih1 + r * 64);
        const ull* p2 = (const ull*)(Whh1 + r * 64);
#pragma unroll
        for (int i = 0; i < 32; i++) w0[i] = p0[i];
#pragma unroll
        for (int i = 0; i < 32; i++) wi1[i] = p1[i];
#pragma unroll
        for (int i = 0; i < 32; i++) wh1[i] = p2[i];
    }
    const float b1 = bih1[r] + bhh1[r];

    if (r < 64) { sh0[r] = 0.0f; sh1[r] = 0.0f; }
    float c0 = 0.0f, c1 = 0.0f;
    float pre = g_pre0[r];          // pre0 for t=0 (prefetched stream below)
    __syncthreads();

    for (int t = 0; t < TM1; t++) {
        // prefetch next step's input preactivation (hides DRAM latency of the 268MB stream)
        const int tn = (t + 1 < TM1) ? (t + 1) : t;
        const float pre_next = g_pre0[(size_t)tn * 256 + r];

        // ---- layer0: g0[r] = pre + dot(W_hh0[r], h0) ----
        ull a0 = 0ull, a1 = 0ull;
        {
            const ulonglong2* hp = (const ulonglong2*)sh0;
#pragma unroll
            for (int i = 0; i < 16; i++) {
                ulonglong2 v = hp[i];
                ffma2(a0, w0[2 * i], v.x);
                ffma2(a1, w0[2 * i + 1], v.y);
            }
        }
        sg[r] = pre + hsum2(a0) + hsum2(a1);
        __syncthreads();

        if (r < 64) {   // layer0 cell update (gate order i,f,g,o)
            float gi = sigm(sg[r]);
            float gf = sigm(sg[r + 64]);
            float gg = tanh_(sg[r + 128]);
            float go = sigm(sg[r + 192]);
            c0 = fmaf(gf, c0, gi * gg);
            sh0[r] = go * tanh_(c0);
        }
        __syncthreads();

        // ---- layer1: g1[r] = b1 + dot(W_ih1[r], h0_t) + dot(W_hh1[r], h1_{t-1}) ----
        a0 = 0ull; a1 = 0ull;
        {
            const ulonglong2* hp = (const ulonglong2*)sh0;
#pragma unroll
            for (int i = 0; i < 16; i++) {
                ulonglong2 v = hp[i];
                ffma2(a0, wi1[2 * i], v.x);
                ffma2(a1, wi1[2 * i + 1], v.y);
            }
            const ulonglong2* hq = (const ulonglong2*)sh1;
#pragma unroll
            for (int i = 0; i < 16; i++) {
                ulonglong2 v = hq[i];
                ffma2(a0, wh1[2 * i], v.x);
                ffma2(a1, wh1[2 * i + 1], v.y);
            }
        }
        sg[r] = b1 + hsum2(a0) + hsum2(a1);
        __syncthreads();

        if (r >= 64 && r < 128) {   // layer1 cell update on warps 2-3
            const int u = r - 64;
            float gi = sigm(sg[u]);
            float gf = sigm(sg[u + 64]);
            float gg = tanh_(sg[u + 128]);
            float go = sigm(sg[u + 192]);
            c1 = fmaf(gf, c1, gi * gg);
            float h = go * tanh_(c1);
            sh1[u] = h;
            g_h2[(size_t)t * 64 + u] = h;   // fire-and-forget trace store
        }
        __syncthreads();

        pre = pre_next;
    }
}

// ---------------- phase 3: parallel FC head ----------------
// out[t][n] = b_fc[n] + sum_k h2[t][k] * W_fc[n][k]
__global__ __launch_bounds__(256)
void fc_kernel(const float* __restrict__ Wfc,
               const float* __restrict__ bfc,
               float* __restrict__ out)
{
    __shared__ float sWT[64 * 64];   // transposed: [k][n] -> conflict-free lane reads
    __shared__ float sh[64 * 64];    // 64 timestep rows

    const int tid = threadIdx.x;
    for (int i = tid; i < 4096; i += 256) {
        int n = i >> 6, k = i & 63;
        sWT[k * 64 + n] = Wfc[i];
    }
    const int tbase = blockIdx.x * 64;
    for (int i = tid; i < 4096; i += 256) {
        int tt = i >> 6, k = i & 63;
        int t = tbase + tt;
        sh[i] = (t < TM1) ? g_h2[(size_t)t * 64 + k] : 0.0f;
    }
    __syncthreads();

    const int n = tid & 63;
    const float bb = bfc[n];
    for (int tt = tid >> 6; tt < 64; tt += 4) {
        const int t = tbase + tt;
        if (t >= TM1) break;
        float acc = bb;
#pragma unroll
        for (int k = 0; k < 64; k++)
            acc = fmaf(sh[tt * 64 + k], sWT[k * 64 + n], acc);
        out[(size_t)t * 64 + n] = acc;
    }
}

// ---------------- launch ----------------
extern "C" void kernel_launch(void* const* d_in, const int* in_sizes, int n_in,
                              void* d_out, int out_size)
{
    const float* y    = (const float*)d_in[0];
    const float* Wih0 = (const float*)d_in[1];
    const float* Whh0 = (const float*)d_in[2];
    const float* bih0 = (const float*)d_in[3];
    const float* bhh0 = (const float*)d_in[4];
    const float* Wih1 = (const float*)d_in[5];
    const float* Whh1 = (const float*)d_in[6];
    const float* bih1 = (const float*)d_in[7];
    const float* bhh1 = (const float*)d_in[8];
    const float* Wfc  = (const float*)d_in[9];
    const float* bfc  = (const float*)d_in[10];
    float* out = (float*)d_out;

    const int preblocks = (TM1 + PRE_TCHUNK - 1) / PRE_TCHUNK;
    pre0_kernel<<<preblocks, 256>>>(y, Wih0, bih0, bhh0);
    lstm_seq_kernel<<<1, 256>>>(Whh0, Wih1, Whh1, bih1, bhh1);
    fc_kernel<<<(TM1 + 63) / 64, 256>>>(Wfc, bfc, out);
}

// round 2
// speedup vs baseline: 1.8237x; 1.8237x over previous
#include <cuda_runtime.h>

#define TM1 262143           // T-1 output timesteps
#define PRE_TCHUNK 128
#define CHUNK 256            // stage-B chunk (steps)
#define NCHUNKS ((TM1 + CHUNK - 1) / CHUNK)   // 1024
#define NB 6                 // stage-B helper CTAs
#define GRID_MEGA (2 + NB)

typedef unsigned long long ull;

// Scratch (allocation-free rule: __device__ globals)
__device__ float g_pre0[(size_t)TM1 * 256];   // layer0 input-side preactivations [t][4H]
__device__ float g_h0[(size_t)TM1 * 64];      // layer0 hidden trace
__device__ float g_pre1[(size_t)TM1 * 256];   // layer1 input-side preactivations [t][4H]
__device__ float g_h2[(size_t)TM1 * 64];      // layer1 hidden trace for FC
__device__ int   g_progA;                     // stage-A published step count
__device__ int   g_chunk_done[NCHUNKS];       // stage-B per-chunk flags

// ---------------- fast math helpers ----------------
__device__ __forceinline__ void ffma2(ull& acc, ull a, ull b) {
    asm("fma.rn.f32x2 %0, %1, %2, %0;" : "+l"(acc) : "l"(a), "l"(b));
}
__device__ __forceinline__ float hsum4(ull a0, ull a1, ull a2, ull a3) {
    ull s0, s1, s;
    asm("add.rn.f32x2 %0, %1, %2;" : "=l"(s0) : "l"(a0), "l"(a1));
    asm("add.rn.f32x2 %0, %1, %2;" : "=l"(s1) : "l"(a2), "l"(a3));
    asm("add.rn.f32x2 %0, %1, %2;" : "=l"(s)  : "l"(s0), "l"(s1));
    float lo, hi;
    asm("mov.b64 {%0,%1}, %2;" : "=f"(lo), "=f"(hi) : "l"(s));
    return lo + hi;
}
__device__ __forceinline__ float fast_ex2(float x) {
    float r; asm("ex2.approx.f32 %0, %1;" : "=f"(r) : "f"(x)); return r;
}
__device__ __forceinline__ float fast_rcp(float x) {
    float r; asm("rcp.approx.f32 %0, %1;" : "=f"(r) : "f"(x)); return r;
}
// sigmoid via ex2/rcp (err ~2^-22; tanh.approx's 2^-11 is too coarse for 1e-3 over 262k steps)
__device__ __forceinline__ float sigm(float x) {
    return fast_rcp(1.0f + fast_ex2(-1.4426950408889634f * x));
}
__device__ __forceinline__ float tanh_(float x) {
    float e = fast_ex2(2.8853900817779268f * x);
    return 1.0f - 2.0f * fast_rcp(e + 1.0f);
}

// ---------------- cross-CTA sync primitives ----------------
__device__ __forceinline__ int ld_acq(const int* p) {
    int v; asm volatile("ld.global.acquire.gpu.b32 %0, [%1];" : "=r"(v) : "l"(p)); return v;
}
__device__ __forceinline__ void st_rel(int* p, int v) {
    asm volatile("st.global.release.gpu.b32 [%0], %1;" :: "l"(p), "r"(v) : "memory");
}

// 64-dot of packed weight row w[32] against 16B-aligned smem vector h[64].
// 4 accumulator chains of depth 8 (latency ~32 cyc vs 64 for 2 chains).
__device__ __forceinline__ float dot64(const ull* __restrict__ w, const float* __restrict__ hvec) {
    ull a0 = 0ull, a1 = 0ull, a2 = 0ull, a3 = 0ull;
    const ulonglong2* hp = (const ulonglong2*)hvec;
#pragma unroll
    for (int i = 0; i < 16; i += 2) {
        ulonglong2 va = hp[i];
        ulonglong2 vb = hp[i + 1];
        ffma2(a0, w[2 * i],     va.x);
        ffma2(a1, w[2 * i + 1], va.y);
        ffma2(a2, w[2 * i + 2], vb.x);
        ffma2(a3, w[2 * i + 3], vb.y);
    }
    return hsum4(a0, a1, a2, a3);
}

// ---------------- init: reset cross-CTA sync state (graph replays!) ----------------
__global__ void init_sync_kernel() {
    int i = blockIdx.x * blockDim.x + threadIdx.x;
    if (i == 0) g_progA = 0;
    if (i < NCHUNKS) g_chunk_done[i] = 0;
}

// ---------------- phase 1: parallel input-side preactivations (layer0) ----------------
__global__ __launch_bounds__(256)
void pre0_kernel(const float* __restrict__ y,
                 const float* __restrict__ Wih0,
                 const float* __restrict__ bih0,
                 const float* __restrict__ bhh0)
{
    __shared__ float sy[PRE_TCHUNK + 8];
    const int r = threadIdx.x;
    const int t0 = blockIdx.x * PRE_TCHUNK;
    int t1 = t0 + PRE_TCHUNK; if (t1 > TM1) t1 = TM1;

    for (int i = r; i < PRE_TCHUNK + 5; i += 256) {
        int idx = t0 + i;                    // padded index
        sy[i] = (idx < 5) ? 1.0f : y[idx - 5];
    }

    float w[6];
#pragma unroll
    for (int j = 0; j < 6; j++) w[j] = Wih0[r * 6 + j];
    const float b = bih0[r] + bhh0[r];
    __syncthreads();

    for (int t = t0; t < t1; t++) {
        float acc = b;
#pragma unroll
        for (int j = 0; j < 6; j++)
            acc = fmaf(w[j], sy[t - t0 + j], acc);
        g_pre0[(size_t)t * 256 + r] = acc;
    }
}

// ---------------- stage A: layer0 recurrence (1 CTA) ----------------
__device__ void stageA(const float* __restrict__ Whh0)
{
    __shared__ __align__(16) float sh0[64];
    __shared__ float sg[256];
    const int r = threadIdx.x;

    ull w[32];
    {
        const ull* p = (const ull*)(Whh0 + r * 64);
#pragma unroll
        for (int i = 0; i < 32; i++) w[i] = p[i];
    }
    if (r < 64) sh0[r] = 0.0f;
    float c0 = 0.0f;
    // depth-2 prefetch of the pre0 stream (DRAM latency 577 > 1 step)
    float p0 = g_pre0[r];
    float p1 = g_pre0[256 + r];
    __syncthreads();

    for (int t = 0; t < TM1; t++) {
        int tf = t + 2; if (tf > TM1 - 1) tf = TM1 - 1;
        const float p2 = g_pre0[(size_t)tf * 256 + r];

        sg[r] = p0 + dot64(w, sh0);
        __syncthreads();

        if (r < 64) {   // gate order i,f,g,o
            float gi = sigm(sg[r]);
            float gf = sigm(sg[r + 64]);
            float gg = tanh_(sg[r + 128]);
            float go = sigm(sg[r + 192]);
            c0 = fmaf(gf, c0, gi * gg);
            float h = go * tanh_(c0);
            sh0[r] = h;
            g_h0[(size_t)t * 64 + r] = h;   // fire-and-forget trace
        }
        __syncthreads();

        if (((t & 63) == 63) && r == 0) {   // publish progress (cumulative fence pattern)
            __threadfence();
            st_rel(&g_progA, t + 1);
        }
        p0 = p1; p1 = p2;
    }
    if (r == 0) { __threadfence(); st_rel(&g_progA, TM1); }
}

// ---------------- stage B: pre1[t] = b1 + W_ih1 . h0[t]  (NB trailing CTAs) ----------------
__device__ void stageB(int helper,
                       const float* __restrict__ Wih1,
                       const float* __restrict__ bih1,
                       const float* __restrict__ bhh1)
{
    __shared__ __align__(16) float sh[64 * 64];   // 64-step tile of h0
    const int r = threadIdx.x;

    ull w[32];
    {
        const ull* p = (const ull*)(Wih1 + r * 64);
#pragma unroll
        for (int i = 0; i < 32; i++) w[i] = p[i];
    }
    const float b1 = bih1[r] + bhh1[r];

    for (int c = helper; c < NCHUNKS; c += NB) {
        const int t0 = c * CHUNK;
        int t1 = t0 + CHUNK; if (t1 > TM1) t1 = TM1;

        while (ld_acq(&g_progA) < t1) __nanosleep(256);

        for (int tb = t0; tb < t1; tb += 64) {
            const int cnt = min(64, t1 - tb);
            __syncthreads();
            for (int i = r; i < cnt * 64; i += 256)
                sh[i] = g_h0[(size_t)tb * 64 + i];
            __syncthreads();
            for (int tt = 0; tt < cnt; tt++)
                g_pre1[(size_t)(tb + tt) * 256 + r] = b1 + dot64(w, sh + tt * 64);
        }
        __syncthreads();
        if (r == 0) { __threadfence(); st_rel(&g_chunk_done[c], 1); }
    }
}

// ---------------- stage C: layer1 recurrence (1 CTA) ----------------
__device__ void stageC(const float* __restrict__ Whh1)
{
    __shared__ __align__(16) float sh1[64];
    __shared__ float sg[256];
    const int r = threadIdx.x;

    ull w[32];
    {
        const ull* p = (const ull*)(Whh1 + r * 64);
#pragma unroll
        for (int i = 0; i < 32; i++) w[i] = p[i];
    }
    if (r < 64) sh1[r] = 0.0f;
    float c1 = 0.0f;

    while (ld_acq(&g_chunk_done[0]) == 0) __nanosleep(256);
    float p0 = g_pre1[r];
    float p1 = g_pre1[256 + r];
    __syncthreads();

    for (int t = 0; t < TM1; t++) {
        int tf = t + 2;
        if (tf <= TM1 - 1 && (tf & (CHUNK - 1)) == 0) {
            const int ch = tf >> 8;     // CHUNK == 256
            while (ld_acq(&g_chunk_done[ch]) == 0) __nanosleep(128);
        }
        if (tf > TM1 - 1) tf = TM1 - 1;
        const float p2 = g_pre1[(size_t)tf * 256 + r];   // L2-hot (B writes ~1 chunk ahead)

        sg[r] = p0 + dot64(w, sh1);
        __syncthreads();

        if (r < 64) {
            float gi = sigm(sg[r]);
            float gf = sigm(sg[r + 64]);
            float gg = tanh_(sg[r + 128]);
            float go = sigm(sg[r + 192]);
            c1 = fmaf(gf, c1, gi * gg);
            float h = go * tanh_(c1);
            sh1[r] = h;
            g_h2[(size_t)t * 64 + r] = h;
        }
        __syncthreads();
        p0 = p1; p1 = p2;
    }
}

// ---------------- pipelined serial phase: 8 co-resident CTAs ----------------
__global__ __launch_bounds__(256, 1)
void lstm_pipe_kernel(const float* __restrict__ Whh0,
                      const float* __restrict__ Wih1,
                      const float* __restrict__ Whh1,
                      const float* __restrict__ bih1,
                      const float* __restrict__ bhh1)
{
    if (blockIdx.x == 0)       stageA(Whh0);
    else if (blockIdx.x == 1)  stageC(Whh1);
    else                       stageB(blockIdx.x - 2, Wih1, bih1, bhh1);
}

// ---------------- phase 3: parallel FC head ----------------
__global__ __launch_bounds__(256)
void fc_kernel(const float* __restrict__ Wfc,
               const float* __restrict__ bfc,
               float* __restrict__ out)
{
    __shared__ float sWT[64 * 64];   // transposed: [k][n]
    __shared__ float sh[64 * 64];    // 64 timestep rows

    const int tid = threadIdx.x;
    for (int i = tid; i < 4096; i += 256) {
        int n = i >> 6, k = i & 63;
        sWT[k * 64 + n] = Wfc[i];
    }
    const int tbase = blockIdx.x * 64;
    for (int i = tid; i < 4096; i += 256) {
        int tt = i >> 6, k = i & 63;
        int t = tbase + tt;
        sh[i] = (t < TM1) ? g_h2[(size_t)t * 64 + k] : 0.0f;
    }
    __syncthreads();

    const int n = tid & 63;
    const float bb = bfc[n];
    for (int tt = tid >> 6; tt < 64; tt += 4) {
        const int t = tbase + tt;
        if (t >= TM1) break;
        float acc = bb;
#pragma unroll
        for (int k = 0; k < 64; k++)
            acc = fmaf(sh[tt * 64 + k], sWT[k * 64 + n], acc);
        out[(size_t)t * 64 + n] = acc;
    }
}

// ---------------- launch ----------------
extern "C" void kernel_launch(void* const* d_in, const int* in_sizes, int n_in,
                              void* d_out, int out_size)
{
    const float* y    = (const float*)d_in[0];
    const float* Wih0 = (const float*)d_in[1];
    const float* Whh0 = (const float*)d_in[2];
    const float* bih0 = (const float*)d_in[3];
    const float* bhh0 = (const float*)d_in[4];
    const float* Wih1 = (const float*)d_in[5];
    const float* Whh1 = (const float*)d_in[6];
    const float* bih1 = (const float*)d_in[7];
    const float* bhh1 = (const float*)d_in[8];
    const float* Wfc  = (const float*)d_in[9];
    const float* bfc  = (const float*)d_in[10];
    float* out = (float*)d_out;

    init_sync_kernel<<<4, 256>>>();
    const int preblocks = (TM1 + PRE_TCHUNK - 1) / PRE_TCHUNK;
    pre0_kernel<<<preblocks, 256>>>(y, Wih0, bih0, bhh0);
    lstm_pipe_kernel<<<GRID_MEGA, 256>>>(Whh0, Wih1, Whh1, bih1, bhh1);
    fc_kernel<<<(TM1 + 63) / 64, 256>>>(Wfc, bfc, out);
}

// round 5
// speedup vs baseline: 1.8666x; 1.0235x over previous
#include <cuda_runtime.h>

#define TM1 262143           // T-1 output timesteps
#define PRE_TCHUNK 128
#define CHUNK 256            // stage-B chunk (steps)
#define NCHUNKS ((TM1 + CHUNK - 1) / CHUNK)   // 1024
#define NB 6                 // stage-B helper CTAs
#define GRID_MEGA (2 + NB)

typedef unsigned long long ull;

// Scratch (+2-step pad so the depth-2 prefetch never needs a clamp branch)
__device__ float g_pre0[(size_t)(TM1 + 2) * 256];
__device__ float g_h0[(size_t)TM1 * 64];
__device__ float g_pre1[(size_t)(TM1 + 2) * 256];
__device__ float g_h2[(size_t)TM1 * 64];
__device__ int   g_progA;
__device__ int   g_chunk_done[NCHUNKS];

// ---------------- fast math helpers ----------------
__device__ __forceinline__ void ffma2(ull& acc, ull a, ull b) {
    asm("fma.rn.f32x2 %0, %1, %2, %0;" : "+l"(acc) : "l"(a), "l"(b));
}
__device__ __forceinline__ float hsum4(ull a0, ull a1, ull a2, ull a3) {
    ull s0, s1, s;
    asm("add.rn.f32x2 %0, %1, %2;" : "=l"(s0) : "l"(a0), "l"(a1));
    asm("add.rn.f32x2 %0, %1, %2;" : "=l"(s1) : "l"(a2), "l"(a3));
    asm("add.rn.f32x2 %0, %1, %2;" : "=l"(s)  : "l"(s0), "l"(s1));
    float lo, hi;
    asm("mov.b64 {%0,%1}, %2;" : "=f"(lo), "=f"(hi) : "l"(s));
    return lo + hi;
}
__device__ __forceinline__ float fast_ex2(float x) {
    float r; asm("ex2.approx.f32 %0, %1;" : "=f"(r) : "f"(x)); return r;
}
__device__ __forceinline__ float fast_rcp(float x) {
    float r; asm("rcp.approx.f32 %0, %1;" : "=f"(r) : "f"(x)); return r;
}

// ---------------- cross-CTA sync ----------------
__device__ __forceinline__ int ld_acq(const int* p) {
    int v; asm volatile("ld.global.acquire.gpu.b32 %0, [%1];" : "=r"(v) : "l"(p)); return v;
}
__device__ __forceinline__ void st_rel(int* p, int v) {
    asm volatile("st.global.release.gpu.b32 [%0], %1;" :: "l"(p), "r"(v) : "memory");
}

// 64-dot of packed weight row w[32] against 16B-aligned smem vector (broadcast loads).
__device__ __forceinline__ float dot64(const ull* __restrict__ w, const float* __restrict__ hvec) {
    ull a0 = 0ull, a1 = 0ull, a2 = 0ull, a3 = 0ull;
    const ulonglong2* hp = (const ulonglong2*)hvec;
#pragma unroll
    for (int i = 0; i < 16; i += 2) {
        ulonglong2 va = hp[i];
        ulonglong2 vb = hp[i + 1];
        ffma2(a0, w[2 * i],     va.x);
        ffma2(a1, w[2 * i + 1], va.y);
        ffma2(a2, w[2 * i + 2], vb.x);
        ffma2(a3, w[2 * i + 3], vb.y);
    }
    return hsum4(a0, a1, a2, a3);
}

// ---------------- init: reset cross-CTA sync state (graph replays!) ----------------
__global__ void init_sync_kernel() {
    int i = blockIdx.x * blockDim.x + threadIdx.x;
    if (i == 0) g_progA = 0;
    if (i < NCHUNKS) g_chunk_done[i] = 0;
}

// ---------------- phase 1: layer0 input-side preactivations ----------------
__global__ __launch_bounds__(256)
void pre0_kernel(const float* __restrict__ y,
                 const float* __restrict__ Wih0,
                 const float* __restrict__ bih0,
                 const float* __restrict__ bhh0)
{
    __shared__ float sy[PRE_TCHUNK + 8];
    const int r = threadIdx.x;
    const int t0 = blockIdx.x * PRE_TCHUNK;
    int t1 = t0 + PRE_TCHUNK; if (t1 > TM1) t1 = TM1;

    for (int i = r; i < PRE_TCHUNK + 5; i += 256) {
        int idx = t0 + i;                    // padded index
        sy[i] = (idx < 5) ? 1.0f : y[idx - 5];
    }

    float w[6];
#pragma unroll
    for (int j = 0; j < 6; j++) w[j] = Wih0[r * 6 + j];
    const float b = bih0[r] + bhh0[r];
    __syncthreads();

    for (int t = t0; t < t1; t++) {
        float acc = b;
#pragma unroll
        for (int j = 0; j < 6; j++)
            acc = fmaf(w[j], sy[t - t0 + j], acc);
        g_pre0[(size_t)t * 256 + r] = acc;
    }
}

// ============ shared recurrence core ============
// Lane mapping: warp w, lane l -> gate g=l>>3, unit u=8w+(l&7), gate-row r=64g+u.
// All 4 gates of unit u live in one warp -> shfl exchange.
// DOUBLE-BUFFERED hidden state: step t reads shb[t&1], writes shb[(t+1)&1],
// then ONE __syncthreads(). Read/write buffers are disjoint -> no race.
#define LOG2E    1.4426950408889634f
#define TWOLOG2E 2.8853900817779268f

template<bool IS_C>
__device__ void recurrence(const float* __restrict__ Whh,
                           const float* __restrict__ preBuf,
                           float* __restrict__ hTrace)
{
    __shared__ __align__(16) float shb[2][64];
    const int tid = threadIdx.x;
    const int wv  = tid >> 5;
    const int l   = tid & 31;
    const int g   = l >> 3;
    const int u8  = l & 7;
    const int u   = 8 * wv + u8;
    const int r   = 64 * g + u;

    ull w[32];
    {
        const ull* p = (const ull*)(Whh + r * 64);
#pragma unroll
        for (int i = 0; i < 32; i++) w[i] = p[i];
    }
    // per-lane activation constants: g==2 -> tanh, else sigmoid
    const float am = (g == 2) ? TWOLOG2E : -LOG2E;
    const float aa = (g == 2) ? 1.0f : 0.0f;
    const float ab = (g == 2) ? -2.0f : 1.0f;

    if (l < 8) { shb[0][u] = 0.0f; }
    float c = 0.0f;

    if (IS_C) {  // wait for first pre1 chunk
        while (ld_acq(&g_chunk_done[0]) == 0) __nanosleep(256);
    }
    float p0 = preBuf[r];
    float p1 = preBuf[256 + r];
    __syncthreads();

    for (int t = 0; t < TM1; t++) {
        const int tf = t + 2;
        if (IS_C) {
            if (tf < TM1 && (tf & (CHUNK - 1)) == 0) {
                const int ch = tf >> 8;
                while (ld_acq(&g_chunk_done[ch]) == 0) __nanosleep(128);
            }
        }
        const float p2 = preBuf[(size_t)tf * 256 + r];   // padded buffer: no clamp

        const float* rd = shb[t & 1];
        float*       wr = shb[(t + 1) & 1];

        const float v = p0 + dot64(w, rd);
        // gate nonlinearity (1 ex2 + 1 rcp warp-instr covers all 4 gate types)
        const float e   = fast_ex2(am * v);
        const float act = fmaf(ab, fast_rcp(e + 1.0f), aa);
        // gather the 4 gates of unit u (all lanes, redundant -> zero divergence)
        const float gi = __shfl_sync(0xffffffffu, act, u8);
        const float gf = __shfl_sync(0xffffffffu, act, u8 + 8);
        const float gg = __shfl_sync(0xffffffffu, act, u8 + 16);
        const float go = __shfl_sync(0xffffffffu, act, u8 + 24);
        c = fmaf(gf, c, gi * gg);
        const float e2 = fast_ex2(TWOLOG2E * c);
        const float th = fmaf(-2.0f, fast_rcp(e2 + 1.0f), 1.0f);
        const float h  = go * th;

        if (l < 8) {                       // predicated short stores (disjoint buffer)
            wr[u] = h;
            hTrace[(size_t)t * 64 + u] = h;
        }
        __syncthreads();                   // orders wr-writes before next step's reads

        if (!IS_C) {
            if (((t & 63) == 63) && tid == 0) {   // publish progress
                __threadfence();
                st_rel(&g_progA, t + 1);
            }
        }
        p0 = p1; p1 = p2;
    }
    if (!IS_C) {
        if (tid == 0) { __threadfence(); st_rel(&g_progA, TM1); }
    }
}

// ---------------- stage B: pre1[t] = b1 + W_ih1 . h0[t]  (NB trailing CTAs) ----------------
__device__ void stageB(int helper,
                       const float* __restrict__ Wih1,
                       const float* __restrict__ bih1,
                       const float* __restrict__ bhh1)
{
    __shared__ __align__(16) float sh[64 * 64];   // 64-step tile of h0
    const int r = threadIdx.x;

    ull w[32];
    {
        const ull* p = (const ull*)(Wih1 + r * 64);
#pragma unroll
        for (int i = 0; i < 32; i++) w[i] = p[i];
    }
    const float b1 = bih1[r] + bhh1[r];

    for (int c = helper; c < NCHUNKS; c += NB) {
        const int t0 = c * CHUNK;
        int t1 = t0 + CHUNK; if (t1 > TM1) t1 = TM1;

        while (ld_acq(&g_progA) < t1) __nanosleep(256);

        for (int tb = t0; tb < t1; tb += 64) {
            const int cnt = min(64, t1 - tb);
            __syncthreads();
            for (int i = r; i < cnt * 64; i += 256)
                sh[i] = g_h0[(size_t)tb * 64 + i];
            __syncthreads();
            for (int tt = 0; tt < cnt; tt++)
                g_pre1[(size_t)(tb + tt) * 256 + r] = b1 + dot64(w, sh + tt * 64);
        }
        __syncthreads();
        if (r == 0) { __threadfence(); st_rel(&g_chunk_done[c], 1); }
    }
}

// ---------------- pipelined serial phase: 8 co-resident CTAs ----------------
__global__ __launch_bounds__(256, 1)
void lstm_pipe_kernel(const float* __restrict__ Whh0,
                      const float* __restrict__ Wih1,
                      const float* __restrict__ Whh1,
                      const float* __restrict__ bih1,
                      const float* __restrict__ bhh1)
{
    if (blockIdx.x == 0)       recurrence<false>(Whh0, g_pre0, g_h0);
    else if (blockIdx.x == 1)  recurrence<true >(Whh1, g_pre1, g_h2);
    else                       stageB(blockIdx.x - 2, Wih1, bih1, bhh1);
}

// ---------------- phase 3: parallel FC head ----------------
__global__ __launch_bounds__(256)
void fc_kernel(const float* __restrict__ Wfc,
               const float* __restrict__ bfc,
               float* __restrict__ out)
{
    __shared__ float sWT[64 * 64];
    __shared__ float sh[64 * 64];

    const int tid = threadIdx.x;
    for (int i = tid; i < 4096; i += 256) {
        int n = i >> 6, k = i & 63;
        sWT[k * 64 + n] = Wfc[i];
    }
    const int tbase = blockIdx.x * 64;
    for (int i = tid; i < 4096; i += 256) {
        int tt = i >> 6, k = i & 63;
        int t = tbase + tt;
        sh[i] = (t < TM1) ? g_h2[(size_t)t * 64 + k] : 0.0f;
    }
    __syncthreads();

    const int n = tid & 63;
    const float bb = bfc[n];
    for (int tt = tid >> 6; tt < 64; tt += 4) {
        const int t = tbase + tt;
        if (t >= TM1) break;
        float acc = bb;
#pragma unroll
        for (int k = 0; k < 64; k++)
            acc = fmaf(sh[tt * 64 + k], sWT[k * 64 + n], acc);
        out[(size_t)t * 64 + n] = acc;
    }
}

// ---------------- launch ----------------
extern "C" void kernel_launch(void* const* d_in, const int* in_sizes, int n_in,
                              void* d_out, int out_size)
{
    const float* y    = (const float*)d_in[0];
    const float* Wih0 = (const float*)d_in[1];
    const float* Whh0 = (const float*)d_in[2];
    const float* bih0 = (const float*)d_in[3];
    const float* bhh0 = (const float*)d_in[4];
    const float* Wih1 = (const float*)d_in[5];
    const float* Whh1 = (const float*)d_in[6];
    const float* bih1 = (const float*)d_in[7];
    const float* bhh1 = (const float*)d_in[8];
    const float* Wfc  = (const float*)d_in[9];
    const float* bfc  = (const float*)d_in[10];
    float* out = (float*)d_out;

    init_sync_kernel<<<4, 256>>>();
    const int preblocks = (TM1 + PRE_TCHUNK - 1) / PRE_TCHUNK;
    pre0_kernel<<<preblocks, 256>>>(y, Wih0, bih0, bhh0);
    lstm_pipe_kernel<<<GRID_MEGA, 256>>>(Whh0, Wih1, Whh1, bih1, bhh1);
    fc_kernel<<<(TM1 + 63) / 64, 256>>>(Wfc, bfc, out);
}